// round 4
// baseline (speedup 1.0000x reference)
#include <cuda_runtime.h>
#include <cuda_bf16.h>

// out_j = (sum_k (Offset_k*4 + mean_k) * s_k * r[j][k] + T_j*300) / 280
// with s = (S, -S, S) * 20,  r = Rx(pi*Rx)·Ry(pi*Ry)·Rz(pi*Rz).
// Folded per batch into A[j][k] = s_k*r[j][k]/280 and t_j = T_j*300/280.
// Params are computed per-block (thread 0, redundant across the 32 blocks of a
// batch) while the first wave of LDGs is in flight — removes the separate
// setup kernel + launch from the graph.

#define PI_F 3.14159265358979323846f

// Scratch for the scalar fallback path only (no cudaMalloc allowed).
__device__ float g_params[4096 * 16];

__device__ __forceinline__ void compute_params(const float* __restrict__ R,
                                               const float* __restrict__ T,
                                               const float* __restrict__ S,
                                               int b, float* p) {
    float sx, cx, sy, cy, sz, cz;
    sincosf(R[b * 3 + 0] * PI_F, &sx, &cx);
    sincosf(R[b * 3 + 1] * PI_F, &sy, &cy);
    sincosf(R[b * 3 + 2] * PI_F, &sz, &cz);

    // r = rx @ ry @ rz  (matching the JAX reference exactly)
    float r00 = cy * cz;
    float r01 = cy * sz;
    float r02 = -sy;
    float r10 = sx * sy * cz - cx * sz;
    float r11 = cx * cz + sx * sy * sz;
    float r12 = sx * cy;
    float r20 = cx * sy * cz + sx * sz;
    float r21 = cx * sy * sz - sx * cz;
    float r22 = cx * cy;

    float sc = S[b] * (20.0f / 280.0f);   // S_SCALE=20 folded with /280
    p[0] = r00 * sc;  p[1] = -r01 * sc;  p[2] = r02 * sc;
    p[3] = r10 * sc;  p[4] = -r11 * sc;  p[5] = r12 * sc;
    p[6] = r20 * sc;  p[7] = -r21 * sc;  p[8] = r22 * sc;
    p[9]  = T[b * 3 + 0] * (300.0f / 280.0f);
    p[10] = T[b * 3 + 1] * (300.0f / 280.0f);
    p[11] = T[b * 3 + 2] * (300.0f / 280.0f);
}

#define XFORM_LANE(V0, V1, V2, O0, O1, O2)                                   \
    do {                                                                     \
        O0 = fmaf(V0, A00, fmaf(V1, A01, fmaf(V2, A02, t0)));                \
        O1 = fmaf(V0, A10, fmaf(V1, A11, fmaf(V2, A12, t1)));                \
        O2 = fmaf(V0, A20, fmaf(V1, A21, fmaf(V2, A22, t2)));                \
    } while (0)

#define XFORM_QUAD(O0, O1, O2, M0, M1, M2, E0, E1, E2)                       \
    do {                                                                     \
        {                                                                    \
            float v0 = fmaf(O0.x, 4.f, M0.x);                                \
            float v1 = fmaf(O1.x, 4.f, M1.x);                                \
            float v2 = fmaf(O2.x, 4.f, M2.x);                                \
            XFORM_LANE(v0, v1, v2, E0.x, E1.x, E2.x);                        \
        }                                                                    \
        {                                                                    \
            float v0 = fmaf(O0.y, 4.f, M0.y);                                \
            float v1 = fmaf(O1.y, 4.f, M1.y);                                \
            float v2 = fmaf(O2.y, 4.f, M2.y);                                \
            XFORM_LANE(v0, v1, v2, E0.y, E1.y, E2.y);                        \
        }                                                                    \
        {                                                                    \
            float v0 = fmaf(O0.z, 4.f, M0.z);                                \
            float v1 = fmaf(O1.z, 4.f, M1.z);                                \
            float v2 = fmaf(O2.z, 4.f, M2.z);                                \
            XFORM_LANE(v0, v1, v2, E0.z, E1.z, E2.z);                        \
        }                                                                    \
        {                                                                    \
            float v0 = fmaf(O0.w, 4.f, M0.w);                                \
            float v1 = fmaf(O1.w, 4.f, M1.w);                                \
            float v2 = fmaf(O2.w, 4.f, M2.w);                                \
            XFORM_LANE(v0, v1, v2, E0.w, E1.w, E2.w);                        \
        }                                                                    \
    } while (0)

// Fused streaming kernel. ITEMS float4-quads per thread.
// Offset/out are touch-once -> evict-first (.cs); mean is reused by every
// batch -> keep L2-resident (__ldg / default policy).
template <int ITEMS>
__global__ __launch_bounds__(256, 6)
void transform_fused_kernel(const float4* __restrict__ off,
                            const float4* __restrict__ mean4,
                            float4* __restrict__ out,
                            const float* __restrict__ R,
                            const float* __restrict__ T,
                            const float* __restrict__ S,
                            int quads,            // pixels/4 per channel
                            int blocks_per_batch) {
    __shared__ float sp[12];

    int b  = blockIdx.x / blocks_per_batch;
    int rb = blockIdx.x - b * blocks_per_batch;
    int q0 = rb * (256 * ITEMS) + threadIdx.x;
    int cbase = b * 3 * quads;

    // Item-0 loads issued BEFORE the barrier: in flight while thread 0 does
    // the (block-redundant) trig.
    float4 o0 = __ldcs(off + cbase + q0);
    float4 o1 = __ldcs(off + cbase + quads + q0);
    float4 o2 = __ldcs(off + cbase + 2 * quads + q0);
    float4 m0 = __ldg(mean4 + q0);
    float4 m1 = __ldg(mean4 + quads + q0);
    float4 m2 = __ldg(mean4 + 2 * quads + q0);

    if (threadIdx.x == 0) {
        compute_params(R, T, S, b, sp);
    }
    __syncthreads();

    float A00 = sp[0], A01 = sp[1], A02 = sp[2];
    float A10 = sp[3], A11 = sp[4], A12 = sp[5];
    float A20 = sp[6], A21 = sp[7], A22 = sp[8];
    float t0 = sp[9], t1 = sp[10], t2 = sp[11];

    // Item 0
    {
        float4 e0, e1, e2;
        XFORM_QUAD(o0, o1, o2, m0, m1, m2, e0, e1, e2);
        __stcs(out + cbase + q0, e0);
        __stcs(out + cbase + quads + q0, e1);
        __stcs(out + cbase + 2 * quads + q0, e2);
    }

    // Remaining items
#pragma unroll
    for (int it = 1; it < ITEMS; ++it) {
        int q = q0 + it * 256;
        float4 p0 = __ldcs(off + cbase + q);
        float4 p1 = __ldcs(off + cbase + quads + q);
        float4 p2 = __ldcs(off + cbase + 2 * quads + q);
        float4 n0 = __ldg(mean4 + q);
        float4 n1 = __ldg(mean4 + quads + q);
        float4 n2 = __ldg(mean4 + 2 * quads + q);

        float4 e0, e1, e2;
        XFORM_QUAD(p0, p1, p2, n0, n1, n2, e0, e1, e2);
        __stcs(out + cbase + q, e0);
        __stcs(out + cbase + quads + q, e1);
        __stcs(out + cbase + 2 * quads + q, e2);
    }
}

// ---------- Scalar fallback path (non-divisible shapes) ----------

__global__ void setup_params_kernel(const float* __restrict__ R,
                                    const float* __restrict__ T,
                                    const float* __restrict__ S,
                                    int B) {
    int b = blockIdx.x * blockDim.x + threadIdx.x;
    if (b >= B) return;
    float p[12];
    compute_params(R, T, S, b, p);
    float* g = g_params + b * 16;
#pragma unroll
    for (int i = 0; i < 12; ++i) g[i] = p[i];
    g[12] = g[13] = g[14] = g[15] = 0.f;
}

__global__ __launch_bounds__(256)
void transform_scalar_kernel(const float* __restrict__ off,
                             const float* __restrict__ mean,
                             float* __restrict__ out,
                             int B, int pixels) {
    long total = (long)B * pixels;
    long stride = (long)gridDim.x * blockDim.x;
    for (long i = blockIdx.x * (long)blockDim.x + threadIdx.x; i < total; i += stride) {
        int b = (int)(i / pixels);
        int n = (int)(i - (long)b * pixels);
        const float* __restrict__ p = g_params + b * 16;
        long cb = (long)b * 3 * pixels;
        float v0 = fmaf(off[cb + n],              4.f, mean[n]);
        float v1 = fmaf(off[cb + pixels + n],     4.f, mean[pixels + n]);
        float v2 = fmaf(off[cb + 2 * pixels + n], 4.f, mean[2 * pixels + n]);
        out[cb + n]              = fmaf(v0, p[0], fmaf(v1, p[1], fmaf(v2, p[2], p[9])));
        out[cb + pixels + n]     = fmaf(v0, p[3], fmaf(v1, p[4], fmaf(v2, p[5], p[10])));
        out[cb + 2 * pixels + n] = fmaf(v0, p[6], fmaf(v1, p[7], fmaf(v2, p[8], p[11])));
    }
}

extern "C" void kernel_launch(void* const* d_in, const int* in_sizes, int n_in,
                              void* d_out, int out_size) {
    const float* Offset = (const float*)d_in[0];   // (B, 3, 256, 256)
    const float* R      = (const float*)d_in[1];   // (B, 3)
    const float* T      = (const float*)d_in[2];   // (B, 1, 3)
    const float* S      = (const float*)d_in[3];   // (B, 1)
    const float* mean   = (const float*)d_in[4];   // (3, 256, 256)
    float* out          = (float*)d_out;

    int B      = in_sizes[1] / 3;
    int pixels = in_sizes[4] / 3;   // 65536

    constexpr int ITEMS = 2;
    if ((pixels % 4) == 0 && ((pixels / 4) % (256 * ITEMS)) == 0) {
        int quads = pixels / 4;
        int blocks_per_batch = quads / (256 * ITEMS);   // 32 for 256x256
        transform_fused_kernel<ITEMS><<<B * blocks_per_batch, 256>>>(
            (const float4*)Offset, (const float4*)mean, (float4*)out,
            R, T, S, quads, blocks_per_batch);
    } else {
        setup_params_kernel<<<(B + 255) / 256, 256>>>(R, T, S, B);
        long total = (long)B * pixels;
        int blocks = (int)((total + 255) / 256);
        if (blocks > 65535 * 32) blocks = 65535 * 32;
        transform_scalar_kernel<<<blocks, 256>>>(Offset, mean, out, B, pixels);
    }
}

// round 6
// speedup vs baseline: 1.0588x; 1.0588x over previous
#include <cuda_runtime.h>
#include <cuda_bf16.h>

// out_j = (sum_k (Offset_k*4 + mean_k) * s_k * r[j][k] + T_j*300) / 280
// with s = (S, -S, S) * 20,  r = Rx(pi*Rx)·Ry(pi*Ry)·Rz(pi*Rz).
// Folded per batch into A[j][k] = s_k*r[j][k]/280 and t_j = T_j*300/280.
//
// R4 lesson: fusing the per-batch trig into the streaming kernel (barrier +
// cache hints) cost 10.6us of streaming bandwidth. This round: streaming
// kernel is the R3 version verbatim (62.3us @ 5716 GB/s measured); the setup
// kernel is parallelized across SMs instead of running as one block.
// (R5 bench was an infra failure; this is the same kernel resubmitted.)

#define PI_F 3.14159265358979323846f

// Per-batch folded params: 16 floats per batch (9 matrix, 3 bias, 4 pad).
// __device__ global scratch (no cudaMalloc allowed). Supports B up to 4096.
__device__ float g_params[4096 * 16];

__global__ void setup_params_kernel(const float* __restrict__ R,
                                    const float* __restrict__ T,
                                    const float* __restrict__ S,
                                    int B) {
    int b = blockIdx.x * blockDim.x + threadIdx.x;
    if (b >= B) return;

    float ax = R[b * 3 + 0] * PI_F;
    float ay = R[b * 3 + 1] * PI_F;
    float az = R[b * 3 + 2] * PI_F;
    float sx, cx, sy, cy, sz, cz;
    sincosf(ax, &sx, &cx);
    sincosf(ay, &sy, &cy);
    sincosf(az, &sz, &cz);

    // r = rx @ ry @ rz  (matching the JAX reference exactly)
    // rx = [[1,0,0],[0,cx,sx],[0,-sx,cx]]
    // ry = [[cy,0,-sy],[0,1,0],[sy,0,cy]]
    // rz = [[cz,sz,0],[-sz,cz,0],[0,0,1]]
    float r00 = cy * cz;
    float r01 = cy * sz;
    float r02 = -sy;
    float r10 = sx * sy * cz - cx * sz;
    float r11 = cx * cz + sx * sy * sz;
    float r12 = sx * cy;
    float r20 = cx * sy * cz + sx * sz;
    float r21 = cx * sy * sz - sx * cz;
    float r22 = cx * cy;

    float Sv = S[b];
    float sc = Sv * (20.0f / 280.0f);   // S_SCALE=20 folded with /280
    float s0 = sc, s1 = -sc, s2 = sc;

    float* p = g_params + b * 16;
    p[0] = r00 * s0;  p[1] = r01 * s1;  p[2] = r02 * s2;
    p[3] = r10 * s0;  p[4] = r11 * s1;  p[5] = r12 * s2;
    p[6] = r20 * s0;  p[7] = r21 * s1;  p[8] = r22 * s2;
    p[9]  = T[b * 3 + 0] * (300.0f / 280.0f);
    p[10] = T[b * 3 + 1] * (300.0f / 280.0f);
    p[11] = T[b * 3 + 2] * (300.0f / 280.0f);
    p[12] = 0.f; p[13] = 0.f; p[14] = 0.f; p[15] = 0.f;
}

#define XFORM_LANE(V0, V1, V2, O0, O1, O2)                                   \
    do {                                                                     \
        O0 = fmaf(V0, A00, fmaf(V1, A01, fmaf(V2, A02, t0)));                \
        O1 = fmaf(V0, A10, fmaf(V1, A11, fmaf(V2, A12, t1)));                \
        O2 = fmaf(V0, A20, fmaf(V1, A21, fmaf(V2, A22, t2)));                \
    } while (0)

// Vectorized streaming kernel: each thread handles ITEMS float4-quads of one
// batch (6 float4 loads + 3 float4 stores per quad, fully coalesced).
// R3-measured: 62.3us, 5716 GB/s. Do not add barriers or cache hints here.
template <int ITEMS>
__global__ __launch_bounds__(256)
void transform_kernel(const float4* __restrict__ off,
                      const float4* __restrict__ mean,
                      float4* __restrict__ out,
                      int quads,            // pixels/4 per channel
                      int blocks_per_batch) {
    int b  = blockIdx.x / blocks_per_batch;
    int rb = blockIdx.x - b * blocks_per_batch;
    int q0 = rb * (256 * ITEMS) + threadIdx.x;

    const float* __restrict__ p = g_params + b * 16;
    float A00 = p[0], A01 = p[1], A02 = p[2];
    float A10 = p[3], A11 = p[4], A12 = p[5];
    float A20 = p[6], A21 = p[7], A22 = p[8];
    float t0 = p[9], t1 = p[10], t2 = p[11];

    int cbase = b * 3 * quads;

#pragma unroll
    for (int it = 0; it < ITEMS; ++it) {
        int q = q0 + it * 256;
        float4 o0 = off[cbase + q];
        float4 o1 = off[cbase + quads + q];
        float4 o2 = off[cbase + 2 * quads + q];
        float4 m0 = mean[q];
        float4 m1 = mean[quads + q];
        float4 m2 = mean[2 * quads + q];

        float4 e0, e1, e2;
        {
            float v0 = fmaf(o0.x, 4.f, m0.x);
            float v1 = fmaf(o1.x, 4.f, m1.x);
            float v2 = fmaf(o2.x, 4.f, m2.x);
            XFORM_LANE(v0, v1, v2, e0.x, e1.x, e2.x);
        }
        {
            float v0 = fmaf(o0.y, 4.f, m0.y);
            float v1 = fmaf(o1.y, 4.f, m1.y);
            float v2 = fmaf(o2.y, 4.f, m2.y);
            XFORM_LANE(v0, v1, v2, e0.y, e1.y, e2.y);
        }
        {
            float v0 = fmaf(o0.z, 4.f, m0.z);
            float v1 = fmaf(o1.z, 4.f, m1.z);
            float v2 = fmaf(o2.z, 4.f, m2.z);
            XFORM_LANE(v0, v1, v2, e0.z, e1.z, e2.z);
        }
        {
            float v0 = fmaf(o0.w, 4.f, m0.w);
            float v1 = fmaf(o1.w, 4.f, m1.w);
            float v2 = fmaf(o2.w, 4.f, m2.w);
            XFORM_LANE(v0, v1, v2, e0.w, e1.w, e2.w);
        }

        out[cbase + q]             = e0;
        out[cbase + quads + q]     = e1;
        out[cbase + 2 * quads + q] = e2;
    }
}

// Scalar grid-stride fallback for shapes not divisible by the vector tile.
__global__ __launch_bounds__(256)
void transform_scalar_kernel(const float* __restrict__ off,
                             const float* __restrict__ mean,
                             float* __restrict__ out,
                             int B, int pixels) {
    long total = (long)B * pixels;
    long stride = (long)gridDim.x * blockDim.x;
    for (long i = blockIdx.x * (long)blockDim.x + threadIdx.x; i < total; i += stride) {
        int b = (int)(i / pixels);
        int n = (int)(i - (long)b * pixels);
        const float* __restrict__ p = g_params + b * 16;
        long cb = (long)b * 3 * pixels;
        float v0 = fmaf(off[cb + n],              4.f, mean[n]);
        float v1 = fmaf(off[cb + pixels + n],     4.f, mean[pixels + n]);
        float v2 = fmaf(off[cb + 2 * pixels + n], 4.f, mean[2 * pixels + n]);
        out[cb + n]              = fmaf(v0, p[0], fmaf(v1, p[1], fmaf(v2, p[2], p[9])));
        out[cb + pixels + n]     = fmaf(v0, p[3], fmaf(v1, p[4], fmaf(v2, p[5], p[10])));
        out[cb + 2 * pixels + n] = fmaf(v0, p[6], fmaf(v1, p[7], fmaf(v2, p[8], p[11])));
    }
}

extern "C" void kernel_launch(void* const* d_in, const int* in_sizes, int n_in,
                              void* d_out, int out_size) {
    const float* Offset = (const float*)d_in[0];   // (B, 3, 256, 256)
    const float* R      = (const float*)d_in[1];   // (B, 3)
    const float* T      = (const float*)d_in[2];   // (B, 1, 3)
    const float* S      = (const float*)d_in[3];   // (B, 1)
    const float* mean   = (const float*)d_in[4];   // (3, 256, 256)
    float* out          = (float*)d_out;

    int B      = in_sizes[1] / 3;
    int pixels = in_sizes[4] / 3;   // 65536

    // Stage 1: per-batch folded 3x3 matrix + bias.
    // 32-thread blocks spread across SMs (R3 ran this as ONE 256-thread block
    // on a single SM -> several us of serial sincosf; this is ~1us).
    setup_params_kernel<<<(B + 31) / 32, 32>>>(R, T, S, B);

    // Stage 2: streaming transform (R3 version, measured 5716 GB/s).
    constexpr int ITEMS = 2;
    if ((pixels % 4) == 0 && ((pixels / 4) % (256 * ITEMS)) == 0) {
        int quads = pixels / 4;
        int blocks_per_batch = quads / (256 * ITEMS);   // 32 for 256x256
        transform_kernel<ITEMS><<<B * blocks_per_batch, 256>>>(
            (const float4*)Offset, (const float4*)mean, (float4*)out,
            quads, blocks_per_batch);
    } else {
        long total = (long)B * pixels;
        int blocks = (int)((total + 255) / 256);
        if (blocks > 65535 * 32) blocks = 65535 * 32;
        transform_scalar_kernel<<<blocks, 256>>>(Offset, mean, out, B, pixels);
    }
}

// round 7
// speedup vs baseline: 1.0593x; 1.0005x over previous
#include <cuda_runtime.h>
#include <cuda_bf16.h>

// out_j = (sum_k (Offset_k*4 + mean_k) * s_k * r[j][k] + T_j*300) / 280
// with s = (S, -S, S) * 20,  r = Rx(pi*Rx)·Ry(pi*Ry)·Rz(pi*Rz).
// Folded: A[j][k] = s_k * r[j][k] * S*20/280,  t_j = T_j*300/280.
//
// R4 lesson: block-wide __syncthreads behind thread-0 trig + cache hints cost
// 10.6us of streaming bandwidth. R6 lesson: the two-kernel split leaves 7.5us
// of graph-node overhead. This round: single kernel, params computed PER WARP
// (lanes 0-2 do one sincosf each, __shfl_sync broadcast — no barrier, no smem,
// no cache hints). Item-0 loads are issued before the trig so the ~300cyc
// param chain hides under DRAM latency.

#define PI_F 3.14159265358979323846f

// Scratch for the scalar fallback path only (no cudaMalloc allowed).
__device__ float g_params[4096 * 16];

#define XFORM_LANE(V0, V1, V2, O0, O1, O2)                                   \
    do {                                                                     \
        O0 = fmaf(V0, A00, fmaf(V1, A01, fmaf(V2, A02, t0)));                \
        O1 = fmaf(V0, A10, fmaf(V1, A11, fmaf(V2, A12, t1)));                \
        O2 = fmaf(V0, A20, fmaf(V1, A21, fmaf(V2, A22, t2)));                \
    } while (0)

#define XFORM_QUAD(O0, O1, O2, M0, M1, M2, E0, E1, E2)                       \
    do {                                                                     \
        {                                                                    \
            float v0 = fmaf(O0.x, 4.f, M0.x);                                \
            float v1 = fmaf(O1.x, 4.f, M1.x);                                \
            float v2 = fmaf(O2.x, 4.f, M2.x);                                \
            XFORM_LANE(v0, v1, v2, E0.x, E1.x, E2.x);                        \
        }                                                                    \
        {                                                                    \
            float v0 = fmaf(O0.y, 4.f, M0.y);                                \
            float v1 = fmaf(O1.y, 4.f, M1.y);                                \
            float v2 = fmaf(O2.y, 4.f, M2.y);                                \
            XFORM_LANE(v0, v1, v2, E0.y, E1.y, E2.y);                        \
        }                                                                    \
        {                                                                    \
            float v0 = fmaf(O0.z, 4.f, M0.z);                                \
            float v1 = fmaf(O1.z, 4.f, M1.z);                                \
            float v2 = fmaf(O2.z, 4.f, M2.z);                                \
            XFORM_LANE(v0, v1, v2, E0.z, E1.z, E2.z);                        \
        }                                                                    \
        {                                                                    \
            float v0 = fmaf(O0.w, 4.f, M0.w);                                \
            float v1 = fmaf(O1.w, 4.f, M1.w);                                \
            float v2 = fmaf(O2.w, 4.f, M2.w);                                \
            XFORM_LANE(v0, v1, v2, E0.w, E1.w, E2.w);                        \
        }                                                                    \
    } while (0)

template <int ITEMS>
__global__ __launch_bounds__(256)
void transform_fused_kernel(const float4* __restrict__ off,
                            const float4* __restrict__ mean,
                            float4* __restrict__ out,
                            const float* __restrict__ R,
                            const float* __restrict__ T,
                            const float* __restrict__ S,
                            int quads,            // pixels/4 per channel
                            int blocks_per_batch) {
    int b  = blockIdx.x / blocks_per_batch;
    int rb = blockIdx.x - b * blocks_per_batch;
    int q0 = rb * (256 * ITEMS) + threadIdx.x;
    int cbase = b * 3 * quads;
    int lane = threadIdx.x & 31;

    // --- Item-0 main loads issued FIRST (independent of params; in flight
    // while the warp does the trig below). Plain LDG, no hints. ---
    float4 o0 = off[cbase + q0];
    float4 o1 = off[cbase + quads + q0];
    float4 o2 = off[cbase + 2 * quads + q0];
    float4 m0 = mean[q0];
    float4 m1 = mean[quads + q0];
    float4 m2 = mean[2 * quads + q0];

    // --- Warp-level param computation: lanes 0-2 each handle one angle. ---
    float ang = (lane < 3) ? R[b * 3 + lane] * PI_F : 0.0f;
    float s_, c_;
    sincosf(ang, &s_, &c_);
    float sx = __shfl_sync(0xFFFFFFFFu, s_, 0);
    float cx = __shfl_sync(0xFFFFFFFFu, c_, 0);
    float sy = __shfl_sync(0xFFFFFFFFu, s_, 1);
    float cy = __shfl_sync(0xFFFFFFFFu, c_, 1);
    float sz = __shfl_sync(0xFFFFFFFFu, s_, 2);
    float cz = __shfl_sync(0xFFFFFFFFu, c_, 2);

    float tv = (lane < 3) ? T[b * 3 + lane] * (300.0f / 280.0f) : 0.0f;
    float t0 = __shfl_sync(0xFFFFFFFFu, tv, 0);
    float t1 = __shfl_sync(0xFFFFFFFFu, tv, 1);
    float t2 = __shfl_sync(0xFFFFFFFFu, tv, 2);

    float Sv = (lane == 0) ? S[b] : 0.0f;
    float sc = __shfl_sync(0xFFFFFFFFu, Sv, 0) * (20.0f / 280.0f);

    // r = rx @ ry @ rz, column signs (+,-,+) folded (matches JAX reference).
    float A00 = (cy * cz) * sc;
    float A01 = -(cy * sz) * sc;
    float A02 = (-sy) * sc;
    float A10 = (sx * sy * cz - cx * sz) * sc;
    float A11 = -(cx * cz + sx * sy * sz) * sc;
    float A12 = (sx * cy) * sc;
    float A20 = (cx * sy * cz + sx * sz) * sc;
    float A21 = -(cx * sy * sz - sx * cz) * sc;
    float A22 = (cx * cy) * sc;

    // --- Item 0 (preloaded) ---
    {
        float4 e0, e1, e2;
        XFORM_QUAD(o0, o1, o2, m0, m1, m2, e0, e1, e2);
        out[cbase + q0]             = e0;
        out[cbase + quads + q0]     = e1;
        out[cbase + 2 * quads + q0] = e2;
    }

    // --- Remaining items (identical to R3's proven loop body) ---
#pragma unroll
    for (int it = 1; it < ITEMS; ++it) {
        int q = q0 + it * 256;
        float4 p0 = off[cbase + q];
        float4 p1 = off[cbase + quads + q];
        float4 p2 = off[cbase + 2 * quads + q];
        float4 n0 = mean[q];
        float4 n1 = mean[quads + q];
        float4 n2 = mean[2 * quads + q];

        float4 e0, e1, e2;
        XFORM_QUAD(p0, p1, p2, n0, n1, n2, e0, e1, e2);
        out[cbase + q]             = e0;
        out[cbase + quads + q]     = e1;
        out[cbase + 2 * quads + q] = e2;
    }
}

// ---------- Scalar fallback path (non-divisible shapes) ----------

__global__ void setup_params_kernel(const float* __restrict__ R,
                                    const float* __restrict__ T,
                                    const float* __restrict__ S,
                                    int B) {
    int b = blockIdx.x * blockDim.x + threadIdx.x;
    if (b >= B) return;

    float sx, cx, sy, cy, sz, cz;
    sincosf(R[b * 3 + 0] * PI_F, &sx, &cx);
    sincosf(R[b * 3 + 1] * PI_F, &sy, &cy);
    sincosf(R[b * 3 + 2] * PI_F, &sz, &cz);

    float r00 = cy * cz;
    float r01 = cy * sz;
    float r02 = -sy;
    float r10 = sx * sy * cz - cx * sz;
    float r11 = cx * cz + sx * sy * sz;
    float r12 = sx * cy;
    float r20 = cx * sy * cz + sx * sz;
    float r21 = cx * sy * sz - sx * cz;
    float r22 = cx * cy;

    float sc = S[b] * (20.0f / 280.0f);
    float* p = g_params + b * 16;
    p[0] = r00 * sc;  p[1] = -r01 * sc;  p[2] = r02 * sc;
    p[3] = r10 * sc;  p[4] = -r11 * sc;  p[5] = r12 * sc;
    p[6] = r20 * sc;  p[7] = -r21 * sc;  p[8] = r22 * sc;
    p[9]  = T[b * 3 + 0] * (300.0f / 280.0f);
    p[10] = T[b * 3 + 1] * (300.0f / 280.0f);
    p[11] = T[b * 3 + 2] * (300.0f / 280.0f);
    p[12] = 0.f; p[13] = 0.f; p[14] = 0.f; p[15] = 0.f;
}

__global__ __launch_bounds__(256)
void transform_scalar_kernel(const float* __restrict__ off,
                             const float* __restrict__ mean,
                             float* __restrict__ out,
                             int B, int pixels) {
    long total = (long)B * pixels;
    long stride = (long)gridDim.x * blockDim.x;
    for (long i = blockIdx.x * (long)blockDim.x + threadIdx.x; i < total; i += stride) {
        int b = (int)(i / pixels);
        int n = (int)(i - (long)b * pixels);
        const float* __restrict__ p = g_params + b * 16;
        long cb = (long)b * 3 * pixels;
        float v0 = fmaf(off[cb + n],              4.f, mean[n]);
        float v1 = fmaf(off[cb + pixels + n],     4.f, mean[pixels + n]);
        float v2 = fmaf(off[cb + 2 * pixels + n], 4.f, mean[2 * pixels + n]);
        out[cb + n]              = fmaf(v0, p[0], fmaf(v1, p[1], fmaf(v2, p[2], p[9])));
        out[cb + pixels + n]     = fmaf(v0, p[3], fmaf(v1, p[4], fmaf(v2, p[5], p[10])));
        out[cb + 2 * pixels + n] = fmaf(v0, p[6], fmaf(v1, p[7], fmaf(v2, p[8], p[11])));
    }
}

extern "C" void kernel_launch(void* const* d_in, const int* in_sizes, int n_in,
                              void* d_out, int out_size) {
    const float* Offset = (const float*)d_in[0];   // (B, 3, 256, 256)
    const float* R      = (const float*)d_in[1];   // (B, 3)
    const float* T      = (const float*)d_in[2];   // (B, 1, 3)
    const float* S      = (const float*)d_in[3];   // (B, 1)
    const float* mean   = (const float*)d_in[4];   // (3, 256, 256)
    float* out          = (float*)d_out;

    int B      = in_sizes[1] / 3;
    int pixels = in_sizes[4] / 3;   // 65536

    constexpr int ITEMS = 2;
    if ((pixels % 4) == 0 && ((pixels / 4) % (256 * ITEMS)) == 0) {
        int quads = pixels / 4;
        int blocks_per_batch = quads / (256 * ITEMS);   // 32 for 256x256
        transform_fused_kernel<ITEMS><<<B * blocks_per_batch, 256>>>(
            (const float4*)Offset, (const float4*)mean, (float4*)out,
            R, T, S, quads, blocks_per_batch);
    } else {
        setup_params_kernel<<<(B + 31) / 32, 32>>>(R, T, S, B);
        long total = (long)B * pixels;
        int blocks = (int)((total + 255) / 256);
        if (blocks > 65535 * 32) blocks = 65535 * 32;
        transform_scalar_kernel<<<blocks, 256>>>(Offset, mean, out, B, pixels);
    }
}

// round 9
// speedup vs baseline: 1.1098x; 1.0477x over previous
#include <cuda_runtime.h>
#include <cuda_bf16.h>

// out_j = (sum_k (Offset_k*4 + mean_k) * s_k * r[j][k] + T_j*300) / 280
// with s = (S, -S, S) * 20,  r = Rx(pi*Rx)·Ry(pi*Ry)·Rz(pi*Rz).
// Folded: A[j][k] = s_k * r[j][k] * S*20/280,  t_j = T_j*300/280.
//
// R7 finding: total - kernel = ~7us even with ONE kernel node -> fixed graph
// overhead. The only lever left is the streaming kernel itself, stuck at 70%
// DRAM with issue=20-24% => MLP-limited (serial load6/compute/store3, MLP~6).
// This round: ITEMS=4 + explicit prefetch pipeline (next item's 6 loads issued
// before current item's compute/store) -> steady-state MLP~12 per warp.
// (R8 bench was an infra failure; identical kernel resubmitted.)

#define PI_F 3.14159265358979323846f

// Scratch for the scalar fallback path only (no cudaMalloc allowed).
__device__ float g_params[4096 * 16];

#define XFORM_LANE(V0, V1, V2, O0, O1, O2)                                   \
    do {                                                                     \
        O0 = fmaf(V0, A00, fmaf(V1, A01, fmaf(V2, A02, t0)));                \
        O1 = fmaf(V0, A10, fmaf(V1, A11, fmaf(V2, A12, t1)));                \
        O2 = fmaf(V0, A20, fmaf(V1, A21, fmaf(V2, A22, t2)));                \
    } while (0)

#define XFORM_QUAD(O0, O1, O2, M0, M1, M2, E0, E1, E2)                       \
    do {                                                                     \
        {                                                                    \
            float v0 = fmaf(O0.x, 4.f, M0.x);                                \
            float v1 = fmaf(O1.x, 4.f, M1.x);                                \
            float v2 = fmaf(O2.x, 4.f, M2.x);                                \
            XFORM_LANE(v0, v1, v2, E0.x, E1.x, E2.x);                        \
        }                                                                    \
        {                                                                    \
            float v0 = fmaf(O0.y, 4.f, M0.y);                                \
            float v1 = fmaf(O1.y, 4.f, M1.y);                                \
            float v2 = fmaf(O2.y, 4.f, M2.y);                                \
            XFORM_LANE(v0, v1, v2, E0.y, E1.y, E2.y);                        \
        }                                                                    \
        {                                                                    \
            float v0 = fmaf(O0.z, 4.f, M0.z);                                \
            float v1 = fmaf(O1.z, 4.f, M1.z);                                \
            float v2 = fmaf(O2.z, 4.f, M2.z);                                \
            XFORM_LANE(v0, v1, v2, E0.z, E1.z, E2.z);                        \
        }                                                                    \
        {                                                                    \
            float v0 = fmaf(O0.w, 4.f, M0.w);                                \
            float v1 = fmaf(O1.w, 4.f, M1.w);                                \
            float v2 = fmaf(O2.w, 4.f, M2.w);                                \
            XFORM_LANE(v0, v1, v2, E0.w, E1.w, E2.w);                        \
        }                                                                    \
    } while (0)

template <int ITEMS>
__global__ __launch_bounds__(256)
void transform_fused_kernel(const float4* __restrict__ off,
                            const float4* __restrict__ mean,
                            float4* __restrict__ out,
                            const float* __restrict__ R,
                            const float* __restrict__ T,
                            const float* __restrict__ S,
                            int quads,            // pixels/4 per channel
                            int blocks_per_batch) {
    int b  = blockIdx.x / blocks_per_batch;
    int rb = blockIdx.x - b * blocks_per_batch;
    int q0 = rb * (256 * ITEMS) + threadIdx.x;
    int cbase = b * 3 * quads;
    int lane = threadIdx.x & 31;

    // --- Item-0 loads issued FIRST (in flight during the trig below). ---
    float4 a0 = off[cbase + q0];
    float4 a1 = off[cbase + quads + q0];
    float4 a2 = off[cbase + 2 * quads + q0];
    float4 b0 = mean[q0];
    float4 b1 = mean[quads + q0];
    float4 b2 = mean[2 * quads + q0];

    // --- Warp-level param computation: lanes 0-2 each handle one angle. ---
    float ang = (lane < 3) ? R[b * 3 + lane] * PI_F : 0.0f;
    float s_, c_;
    sincosf(ang, &s_, &c_);
    float sx = __shfl_sync(0xFFFFFFFFu, s_, 0);
    float cx = __shfl_sync(0xFFFFFFFFu, c_, 0);
    float sy = __shfl_sync(0xFFFFFFFFu, s_, 1);
    float cy = __shfl_sync(0xFFFFFFFFu, c_, 1);
    float sz = __shfl_sync(0xFFFFFFFFu, s_, 2);
    float cz = __shfl_sync(0xFFFFFFFFu, c_, 2);

    float tv = (lane < 3) ? T[b * 3 + lane] * (300.0f / 280.0f) : 0.0f;
    float t0 = __shfl_sync(0xFFFFFFFFu, tv, 0);
    float t1 = __shfl_sync(0xFFFFFFFFu, tv, 1);
    float t2 = __shfl_sync(0xFFFFFFFFu, tv, 2);

    float Sv = (lane == 0) ? S[b] : 0.0f;
    float sc = __shfl_sync(0xFFFFFFFFu, Sv, 0) * (20.0f / 280.0f);

    // r = rx @ ry @ rz, column signs (+,-,+) folded (matches JAX reference).
    float A00 = (cy * cz) * sc;
    float A01 = -(cy * sz) * sc;
    float A02 = (-sy) * sc;
    float A10 = (sx * sy * cz - cx * sz) * sc;
    float A11 = -(cx * cz + sx * sy * sz) * sc;
    float A12 = (sx * cy) * sc;
    float A20 = (cx * sy * cz + sx * sz) * sc;
    float A21 = -(cx * sy * sz - sx * cz) * sc;
    float A22 = (cx * cy) * sc;

    // --- Pipelined main loop: prefetch item it+1 before computing item it. ---
#pragma unroll
    for (int it = 0; it < ITEMS; ++it) {
        float4 c0, c1, c2, d0, d1, d2;
        if (it + 1 < ITEMS) {
            int qn = q0 + (it + 1) * 256;
            c0 = off[cbase + qn];
            c1 = off[cbase + quads + qn];
            c2 = off[cbase + 2 * quads + qn];
            d0 = mean[qn];
            d1 = mean[quads + qn];
            d2 = mean[2 * quads + qn];
        }

        int q = q0 + it * 256;
        float4 e0, e1, e2;
        XFORM_QUAD(a0, a1, a2, b0, b1, b2, e0, e1, e2);
        out[cbase + q]             = e0;
        out[cbase + quads + q]     = e1;
        out[cbase + 2 * quads + q] = e2;

        if (it + 1 < ITEMS) {
            a0 = c0; a1 = c1; a2 = c2;
            b0 = d0; b1 = d1; b2 = d2;
        }
    }
}

// ---------- Scalar fallback path (non-divisible shapes) ----------

__global__ void setup_params_kernel(const float* __restrict__ R,
                                    const float* __restrict__ T,
                                    const float* __restrict__ S,
                                    int B) {
    int b = blockIdx.x * blockDim.x + threadIdx.x;
    if (b >= B) return;

    float sx, cx, sy, cy, sz, cz;
    sincosf(R[b * 3 + 0] * PI_F, &sx, &cx);
    sincosf(R[b * 3 + 1] * PI_F, &sy, &cy);
    sincosf(R[b * 3 + 2] * PI_F, &sz, &cz);

    float r00 = cy * cz;
    float r01 = cy * sz;
    float r02 = -sy;
    float r10 = sx * sy * cz - cx * sz;
    float r11 = cx * cz + sx * sy * sz;
    float r12 = sx * cy;
    float r20 = cx * sy * cz + sx * sz;
    float r21 = cx * sy * sz - sx * cz;
    float r22 = cx * cy;

    float sc = S[b] * (20.0f / 280.0f);
    float* p = g_params + b * 16;
    p[0] = r00 * sc;  p[1] = -r01 * sc;  p[2] = r02 * sc;
    p[3] = r10 * sc;  p[4] = -r11 * sc;  p[5] = r12 * sc;
    p[6] = r20 * sc;  p[7] = -r21 * sc;  p[8] = r22 * sc;
    p[9]  = T[b * 3 + 0] * (300.0f / 280.0f);
    p[10] = T[b * 3 + 1] * (300.0f / 280.0f);
    p[11] = T[b * 3 + 2] * (300.0f / 280.0f);
    p[12] = 0.f; p[13] = 0.f; p[14] = 0.f; p[15] = 0.f;
}

__global__ __launch_bounds__(256)
void transform_scalar_kernel(const float* __restrict__ off,
                             const float* __restrict__ mean,
                             float* __restrict__ out,
                             int B, int pixels) {
    long total = (long)B * pixels;
    long stride = (long)gridDim.x * blockDim.x;
    for (long i = blockIdx.x * (long)blockDim.x + threadIdx.x; i < total; i += stride) {
        int b = (int)(i / pixels);
        int n = (int)(i - (long)b * pixels);
        const float* __restrict__ p = g_params + b * 16;
        long cb = (long)b * 3 * pixels;
        float v0 = fmaf(off[cb + n],              4.f, mean[n]);
        float v1 = fmaf(off[cb + pixels + n],     4.f, mean[pixels + n]);
        float v2 = fmaf(off[cb + 2 * pixels + n], 4.f, mean[2 * pixels + n]);
        out[cb + n]              = fmaf(v0, p[0], fmaf(v1, p[1], fmaf(v2, p[2], p[9])));
        out[cb + pixels + n]     = fmaf(v0, p[3], fmaf(v1, p[4], fmaf(v2, p[5], p[10])));
        out[cb + 2 * pixels + n] = fmaf(v0, p[6], fmaf(v1, p[7], fmaf(v2, p[8], p[11])));
    }
}

extern "C" void kernel_launch(void* const* d_in, const int* in_sizes, int n_in,
                              void* d_out, int out_size) {
    const float* Offset = (const float*)d_in[0];   // (B, 3, 256, 256)
    const float* R      = (const float*)d_in[1];   // (B, 3)
    const float* T      = (const float*)d_in[2];   // (B, 1, 3)
    const float* S      = (const float*)d_in[3];   // (B, 1)
    const float* mean   = (const float*)d_in[4];   // (3, 256, 256)
    float* out          = (float*)d_out;

    int B      = in_sizes[1] / 3;
    int pixels = in_sizes[4] / 3;   // 65536

    constexpr int ITEMS = 4;
    if ((pixels % 4) == 0 && ((pixels / 4) % (256 * ITEMS)) == 0) {
        int quads = pixels / 4;
        int blocks_per_batch = quads / (256 * ITEMS);   // 16 for 256x256
        transform_fused_kernel<ITEMS><<<B * blocks_per_batch, 256>>>(
            (const float4*)Offset, (const float4*)mean, (float4*)out,
            R, T, S, quads, blocks_per_batch);
    } else {
        setup_params_kernel<<<(B + 31) / 32, 32>>>(R, T, S, B);
        long total = (long)B * pixels;
        int blocks = (int)((total + 255) / 256);
        if (blocks > 65535 * 32) blocks = 65535 * 32;
        transform_scalar_kernel<<<blocks, 256>>>(Offset, mean, out, B, pixels);
    }
}